// round 4
// baseline (speedup 1.0000x reference)
#include <cuda_runtime.h>

// LSTM: B=4096, T=512, IN=1, H=32, OUT=1
// One warp handles THREE batch elements; W_hh rows live once in registers and
// are shared by all three (2x->3x ILP at ~same register cost). Lane j computes
// gate rows i_j,f_j,g_j,o_j. Single FFMA2 chain per gate (12 independent
// chains/warp). Sigmoid gates' weights+bias are pre-scaled by 0.5 so
// sigmoid(x) = fmaf(0.5, tanh.approx(pre), 0.5) with no extra FMUL.

#define TT  512
#define HH  32
#define BB  4096
#define EPW 3

typedef unsigned long long u64;

__device__ __forceinline__ u64 fma2(u64 a, u64 b, u64 c) {
    u64 d;
    asm("fma.rn.f32x2 %0, %1, %2, %3;" : "=l"(d) : "l"(a), "l"(b), "l"(c));
    return d;
}
__device__ __forceinline__ float unpack_sum(u64 v) {
    float lo, hi;
    asm("mov.b64 {%0, %1}, %2;" : "=f"(lo), "=f"(hi) : "l"(v));
    return lo + hi;
}
__device__ __forceinline__ u64 pack2(float lo, float hi) {
    u64 d;
    asm("mov.b64 %0, {%1, %2};" : "=l"(d) : "f"(lo), "f"(hi));
    return d;
}
__device__ __forceinline__ float tanh_hw(float x) {
    float r;
    asm("tanh.approx.f32 %0, %1;" : "=f"(r) : "f"(x));
    return r;
}

__global__ __launch_bounds__(128)
void lstm_warp3_kernel(const float* __restrict__ x,      // [B,T,1]
                       const float* __restrict__ W_ih,   // [4H,1]
                       const float* __restrict__ W_hh,   // [4H,H]
                       const float* __restrict__ b_ih,   // [4H]
                       const float* __restrict__ b_hh,   // [4H]
                       const float* __restrict__ fc_w,   // [1,H]
                       const float* __restrict__ fc_b,   // [1]
                       float* __restrict__ out)          // [B,1]
{
    __shared__ __align__(16) float x_sh[4][EPW][TT];       // 12 elements per CTA
    __shared__ __align__(16) float h_sh[4][2][EPW][HH];    // [warp][buf][elem][j]

    const int tid  = threadIdx.x;
    const int wid  = tid >> 5;
    const int lane = tid & 31;
    const int b0   = (blockIdx.x * 4 + wid) * EPW;

    // Stage the 3 x-sequences (clamped for the tail CTA; coalesced LDG.128).
    #pragma unroll
    for (int e = 0; e < EPW; e++) {
        const int be = min(b0 + e, BB - 1);
        const float4* xb4 = reinterpret_cast<const float4*>(x + (size_t)be * TT);
        float4* xs4 = reinterpret_cast<float4*>(x_sh[wid][e]);
        #pragma unroll
        for (int i = 0; i < TT / 4 / 32; i++)
            xs4[lane + i * 32] = xb4[lane + i * 32];
    }

    // Per-lane weights, shared by all 3 elements. Gates 0,1,3 (i,f,o) are
    // pre-scaled by 0.5 so the sigmoid needs no input FMUL.
    u64   w[4][16];
    float wih[4], bias[4];
    #pragma unroll
    for (int gt = 0; gt < 4; gt++) {
        const int   row   = gt * HH + lane;
        const float scale = (gt == 2) ? 1.0f : 0.5f;
        const float4* wr = reinterpret_cast<const float4*>(W_hh + row * HH);
        #pragma unroll
        for (int q = 0; q < 8; q++) {
            float4 v = wr[q];
            w[gt][2 * q]     = pack2(v.x * scale, v.y * scale);
            w[gt][2 * q + 1] = pack2(v.z * scale, v.w * scale);
        }
        wih[gt]  = W_ih[row] * scale;
        bias[gt] = (b_ih[row] + b_hh[row]) * scale;
    }

    float c[EPW], hj[EPW];
    #pragma unroll
    for (int e = 0; e < EPW; e++) {
        h_sh[wid][0][e][lane] = 0.0f;
        c[e] = 0.0f; hj[e] = 0.0f;
    }
    __syncwarp();

    int p = 0;
    for (int t = 0; t < TT; t++) {
        // acc[e][gt]: single FFMA2 chain per gate; x*W_ih + bias folded in.
        u64 acc[EPW][4];
        #pragma unroll
        for (int e = 0; e < EPW; e++) {
            const float xt = x_sh[wid][e][t];
            #pragma unroll
            for (int gt = 0; gt < 4; gt++)
                acc[e][gt] = pack2(fmaf(xt, wih[gt], bias[gt]), 0.0f);
        }

        #pragma unroll
        for (int q = 0; q < 8; q++) {
            #pragma unroll
            for (int e = 0; e < EPW; e++) {
                // broadcast LDS.128, conflict-free
                ulonglong2 hv = reinterpret_cast<const ulonglong2*>(h_sh[wid][p][e])[q];
                #pragma unroll
                for (int gt = 0; gt < 4; gt++) {
                    acc[e][gt] = fma2(hv.x, w[gt][2 * q],     acc[e][gt]);
                    acc[e][gt] = fma2(hv.y, w[gt][2 * q + 1], acc[e][gt]);
                }
            }
        }

        #pragma unroll
        for (int e = 0; e < EPW; e++) {
            // pre_i/f/o are already 0.5x-scaled -> sigmoid = 0.5*tanh(pre)+0.5
            const float gi = fmaf(0.5f, tanh_hw(unpack_sum(acc[e][0])), 0.5f);
            const float gf = fmaf(0.5f, tanh_hw(unpack_sum(acc[e][1])), 0.5f);
            const float gg = tanh_hw(unpack_sum(acc[e][2]));
            const float go = fmaf(0.5f, tanh_hw(unpack_sum(acc[e][3])), 0.5f);
            c[e]  = fmaf(gf, c[e], gi * gg);
            hj[e] = go * tanh_hw(c[e]);
            h_sh[wid][p ^ 1][e][lane] = hj[e];
        }

        p ^= 1;
        __syncwarp();
    }

    // out[b] = dot(h, fc_w) + fc_b (3 interleaved butterfly reduces).
    const float fw = fc_w[lane];
    float v[EPW];
    #pragma unroll
    for (int e = 0; e < EPW; e++) v[e] = hj[e] * fw;
    #pragma unroll
    for (int off = 16; off > 0; off >>= 1) {
        #pragma unroll
        for (int e = 0; e < EPW; e++)
            v[e] += __shfl_xor_sync(0xffffffffu, v[e], off);
    }
    if (lane == 0) {
        #pragma unroll
        for (int e = 0; e < EPW; e++)
            if (b0 + e < BB) out[b0 + e] = v[e] + fc_b[0];
    }
}

extern "C" void kernel_launch(void* const* d_in, const int* in_sizes, int n_in,
                              void* d_out, int out_size) {
    const float* x    = (const float*)d_in[0];
    const float* W_ih = (const float*)d_in[1];
    const float* W_hh = (const float*)d_in[2];
    const float* b_ih = (const float*)d_in[3];
    const float* b_hh = (const float*)d_in[4];
    const float* fc_w = (const float*)d_in[5];
    const float* fc_b = (const float*)d_in[6];
    float* out = (float*)d_out;

    const int elems_per_cta = 4 * EPW;                      // 12
    const int grid = (BB + elems_per_cta - 1) / elems_per_cta;  // 342
    lstm_warp3_kernel<<<grid, 128>>>(x, W_ih, W_hh, b_ih, b_hh, fc_w, fc_b, out);
}

// round 5
// speedup vs baseline: 1.1683x; 1.1683x over previous
#include <cuda_runtime.h>

// LSTM: B=4096, T=512, IN=1, H=32, OUT=1
// One warp handles FOUR batch elements; W_hh rows live once in registers,
// shared by all four (4x in-warp ILP at fixed weight cost). Lane j computes
// gate rows i_j,f_j,g_j,o_j. Single FFMA2 chain per (elem,gate) -> 16
// independent chains/warp. Sigmoid gates (i,f,o) use 0.5-pre-scaled weights:
// sigmoid(x) = fmaf(0.5, tanh.approx(pre2x), 0.5).
//
// KEY: grid = 4096/(4 warps * 4 elems) = 256 CTAs <= 296 concurrent
// (2 CTAs/SM at ~220 regs) -> SINGLE WAVE. R4's 512us was 2 waves with the
// second wave 15% occupied; this removes it.

#define TT  512
#define HH  32
#define BB  4096
#define EPW 4

typedef unsigned long long u64;

__device__ __forceinline__ u64 fma2(u64 a, u64 b, u64 c) {
    u64 d;
    asm("fma.rn.f32x2 %0, %1, %2, %3;" : "=l"(d) : "l"(a), "l"(b), "l"(c));
    return d;
}
__device__ __forceinline__ float unpack_sum(u64 v) {
    float lo, hi;
    asm("mov.b64 {%0, %1}, %2;" : "=f"(lo), "=f"(hi) : "l"(v));
    return lo + hi;
}
__device__ __forceinline__ u64 pack2(float lo, float hi) {
    u64 d;
    asm("mov.b64 %0, {%1, %2};" : "=l"(d) : "f"(lo), "f"(hi));
    return d;
}
__device__ __forceinline__ float tanh_hw(float x) {
    float r;
    asm("tanh.approx.f32 %0, %1;" : "=f"(r) : "f"(x));
    return r;
}

__global__ __launch_bounds__(128, 2)
void lstm_warp4_kernel(const float* __restrict__ x,      // [B,T,1]
                       const float* __restrict__ W_ih,   // [4H,1]
                       const float* __restrict__ W_hh,   // [4H,H]
                       const float* __restrict__ b_ih,   // [4H]
                       const float* __restrict__ b_hh,   // [4H]
                       const float* __restrict__ fc_w,   // [1,H]
                       const float* __restrict__ fc_b,   // [1]
                       float* __restrict__ out)          // [B,1]
{
    __shared__ __align__(16) float x_sh[4][EPW][TT];       // 16 elements per CTA
    __shared__ __align__(16) float h_sh[4][2][EPW][HH];    // [warp][buf][elem][j]

    const int tid  = threadIdx.x;
    const int wid  = tid >> 5;
    const int lane = tid & 31;
    const int b0   = (blockIdx.x * 4 + wid) * EPW;         // exact: 256*16 = 4096

    // Stage the 4 x-sequences (coalesced LDG.128 per warp).
    #pragma unroll
    for (int e = 0; e < EPW; e++) {
        const float4* xb4 = reinterpret_cast<const float4*>(x + (size_t)(b0 + e) * TT);
        float4* xs4 = reinterpret_cast<float4*>(x_sh[wid][e]);
        #pragma unroll
        for (int i = 0; i < TT / 4 / 32; i++)
            xs4[lane + i * 32] = xb4[lane + i * 32];
    }

    // Per-lane weights, shared by all 4 elements. Gates 0,1,3 (i,f,o) are
    // pre-scaled by 0.5 so the sigmoid needs no input FMUL.
    u64   w[4][16];
    float wih[4], bias[4];
    #pragma unroll
    for (int gt = 0; gt < 4; gt++) {
        const int   row   = gt * HH + lane;
        const float scale = (gt == 2) ? 1.0f : 0.5f;
        const float4* wr = reinterpret_cast<const float4*>(W_hh + row * HH);
        #pragma unroll
        for (int q = 0; q < 8; q++) {
            float4 v = wr[q];
            w[gt][2 * q]     = pack2(v.x * scale, v.y * scale);
            w[gt][2 * q + 1] = pack2(v.z * scale, v.w * scale);
        }
        wih[gt]  = W_ih[row] * scale;
        bias[gt] = (b_ih[row] + b_hh[row]) * scale;
    }

    float c[EPW], hj[EPW];
    #pragma unroll
    for (int e = 0; e < EPW; e++) {
        h_sh[wid][0][e][lane] = 0.0f;
        c[e] = 0.0f; hj[e] = 0.0f;
    }
    __syncwarp();

    int p = 0;
    for (int t = 0; t < TT; t++) {
        // acc[e][gt]: single FFMA2 chain per gate; x*W_ih + bias folded in.
        u64 acc[EPW][4];
        #pragma unroll
        for (int e = 0; e < EPW; e++) {
            const float xt = x_sh[wid][e][t];
            #pragma unroll
            for (int gt = 0; gt < 4; gt++)
                acc[e][gt] = pack2(fmaf(xt, wih[gt], bias[gt]), 0.0f);
        }

        #pragma unroll
        for (int q = 0; q < 8; q++) {
            #pragma unroll
            for (int e = 0; e < EPW; e++) {
                // broadcast LDS.128, conflict-free
                ulonglong2 hv = reinterpret_cast<const ulonglong2*>(h_sh[wid][p][e])[q];
                #pragma unroll
                for (int gt = 0; gt < 4; gt++) {
                    acc[e][gt] = fma2(hv.x, w[gt][2 * q],     acc[e][gt]);
                    acc[e][gt] = fma2(hv.y, w[gt][2 * q + 1], acc[e][gt]);
                }
            }
        }

        #pragma unroll
        for (int e = 0; e < EPW; e++) {
            // pre_i/f/o are already 0.5x-scaled -> sigmoid = 0.5*tanh(pre)+0.5
            const float gi = fmaf(0.5f, tanh_hw(unpack_sum(acc[e][0])), 0.5f);
            const float gf = fmaf(0.5f, tanh_hw(unpack_sum(acc[e][1])), 0.5f);
            const float gg = tanh_hw(unpack_sum(acc[e][2]));
            const float go = fmaf(0.5f, tanh_hw(unpack_sum(acc[e][3])), 0.5f);
            c[e]  = fmaf(gf, c[e], gi * gg);
            hj[e] = go * tanh_hw(c[e]);
            h_sh[wid][p ^ 1][e][lane] = hj[e];
        }

        p ^= 1;
        __syncwarp();
    }

    // out[b] = dot(h, fc_w) + fc_b (4 interleaved butterfly reduces).
    const float fw = fc_w[lane];
    float v[EPW];
    #pragma unroll
    for (int e = 0; e < EPW; e++) v[e] = hj[e] * fw;
    #pragma unroll
    for (int off = 16; off > 0; off >>= 1) {
        #pragma unroll
        for (int e = 0; e < EPW; e++)
            v[e] += __shfl_xor_sync(0xffffffffu, v[e], off);
    }
    if (lane == 0) {
        #pragma unroll
        for (int e = 0; e < EPW; e++)
            out[b0 + e] = v[e] + fc_b[0];
    }
}

extern "C" void kernel_launch(void* const* d_in, const int* in_sizes, int n_in,
                              void* d_out, int out_size) {
    const float* x    = (const float*)d_in[0];
    const float* W_ih = (const float*)d_in[1];
    const float* W_hh = (const float*)d_in[2];
    const float* b_ih = (const float*)d_in[3];
    const float* b_hh = (const float*)d_in[4];
    const float* fc_w = (const float*)d_in[5];
    const float* fc_b = (const float*)d_in[6];
    float* out = (float*)d_out;

    const int grid = BB / (4 * EPW);   // 256 CTAs -> single wave at 2 CTAs/SM
    lstm_warp4_kernel<<<grid, 128>>>(x, W_ih, W_hh, b_ih, b_hh, fc_w, fc_b, out);
}